// round 11
// baseline (speedup 1.0000x reference)
#include <cuda_runtime.h>
#include <cuda_bf16.h>

#define B    4
#define C    256
#define CQK  16
#define MT   64
#define NT   64
#define N    4096
#define NTILES (N / NT)
#define LOG2E 1.4426950408889634f
#define SBIAS 20.0f     // P = 2^(s*log2e - SBIAS); cancels in o/L

typedef unsigned long long u64;
typedef unsigned int u32;
typedef unsigned short u16;
typedef unsigned char u8;

// Scratch: q,k bf16 [B][N][16] (q pre-scaled by log2e); v e4m3 [B][C][N]
__device__ __nv_bfloat16 g_q[(size_t)B * N * CQK];
__device__ __nv_bfloat16 g_k[(size_t)B * N * CQK];
__device__ u8            g_v[(size_t)B * C * N];

// ---- f32x2 helpers (projection) ---------------------------------------------
__device__ __forceinline__ u64 pk2(float lo, float hi) {
    u64 r; asm("mov.b64 %0,{%1,%2};" : "=l"(r) : "f"(lo), "f"(hi)); return r;
}
__device__ __forceinline__ u64 fma2(u64 a, u64 b, u64 c) {
    u64 d; asm("fma.rn.f32x2 %0,%1,%2,%3;" : "=l"(d) : "l"(a), "l"(b), "l"(c)); return d;
}
__device__ __forceinline__ float2 up2(u64 a) {
    float2 f; asm("mov.b64 {%0,%1},%2;" : "=f"(f.x), "=f"(f.y) : "l"(a)); return f;
}

// ---- bf16 / f16 / fp8 helpers --------------------------------------------------
__device__ __forceinline__ u32 bf2(float lo, float hi) {
    u32 r; asm("cvt.rn.bf16x2.f32 %0,%1,%2;" : "=r"(r) : "f"(hi), "f"(lo)); return r;
}
__device__ __forceinline__ u32 hpack(float lo, float hi) {
    u32 r; asm("cvt.rn.f16x2.f32 %0,%1,%2;" : "=r"(r) : "f"(hi), "f"(lo)); return r;
}
__device__ __forceinline__ u32 ex2h2(u32 s) {
    u32 d; asm("ex2.approx.f16x2 %0,%1;" : "=r"(d) : "r"(s)); return d;
}
__device__ __forceinline__ u32 hadd2(u32 a, u32 b) {
    u32 d; asm("add.rn.f16x2 %0,%1,%2;" : "=r"(d) : "r"(a), "r"(b)); return d;
}
__device__ __forceinline__ u16 e4m3h2(u32 h) {
    u16 d; asm("cvt.rn.satfinite.e4m3x2.f16x2 %0,%1;" : "=h"(d) : "r"(h)); return d;
}
__device__ __forceinline__ u16 e4m3f2(float lo, float hi) {
    u16 d; asm("cvt.rn.satfinite.e4m3x2.f32 %0,%1,%2;" : "=h"(d) : "f"(hi), "f"(lo)); return d;
}
__device__ __forceinline__ float h2sum(u32 h) {
    float a, b;
    asm("{.reg .f16 x,y; mov.b32 {x,y},%2; cvt.f32.f16 %0,x; cvt.f32.f16 %1,y;}"
        : "=f"(a), "=f"(b) : "r"(h));
    return a + b;
}

// ---- tensor-core helpers (u32 shared addresses) ---------------------------------
__device__ __forceinline__ u32 smem_u32(const void* p) {
    u32 a;
    asm("{ .reg .u64 t; cvta.to.shared.u64 t, %1; cvt.u32.u64 %0, t; }" : "=r"(a) : "l"(p));
    return a;
}
__device__ __forceinline__ void ldsm4(u32* r, u32 a) {
    asm volatile("ldmatrix.sync.aligned.m8n8.x4.shared.b16 {%0,%1,%2,%3},[%4];"
                 : "=r"(r[0]), "=r"(r[1]), "=r"(r[2]), "=r"(r[3]) : "r"(a));
}
__device__ __forceinline__ void mma_bf16(float* d, const u32* a, const u32* b) {
    asm volatile("mma.sync.aligned.m16n8k16.row.col.f32.bf16.bf16.f32 "
                 "{%0,%1,%2,%3},{%4,%5,%6,%7},{%8,%9},{%0,%1,%2,%3};"
                 : "+f"(d[0]), "+f"(d[1]), "+f"(d[2]), "+f"(d[3])
                 : "r"(a[0]), "r"(a[1]), "r"(a[2]), "r"(a[3]), "r"(b[0]), "r"(b[1]));
}
__device__ __forceinline__ void mma_e4m3(float* d, const u32* a, const u32* b) {
    asm volatile("mma.sync.aligned.m16n8k32.row.col.f32.e4m3.e4m3.f32 "
                 "{%0,%1,%2,%3},{%4,%5,%6,%7},{%8,%9},{%0,%1,%2,%3};"
                 : "+f"(d[0]), "+f"(d[1]), "+f"(d[2]), "+f"(d[3])
                 : "r"(a[0]), "r"(a[1]), "r"(a[2]), "r"(a[3]), "r"(b[0]), "r"(b[1]));
}

// ---------------------------------------------------------------------------
// Projection (unchanged). grid (N/512, B, 9), 256 thr, 2 pixels/thread.
// ---------------------------------------------------------------------------
__global__ __launch_bounds__(256) void proj_kernel(
    const float* __restrict__ x,
    const float* __restrict__ Wq, const float* __restrict__ bq,
    const float* __restrict__ Wk, const float* __restrict__ bk,
    const float* __restrict__ Wv, const float* __restrict__ bv)
{
    __shared__ float w_t[C * 32];   // [c][o]
    const int t = threadIdx.x;
    const int b = blockIdx.y;
    const int z = blockIdx.z;

    if (z < 8) {
        for (int idx = t; idx < C * 32; idx += 256) {
            int c = idx >> 5, o = idx & 31;
            w_t[idx] = Wv[(size_t)(z * 32 + o) * C + c];
        }
    } else {
        for (int idx = t; idx < C * 32; idx += 256) {
            int c = idx >> 5, o = idx & 31;
            w_t[idx] = (o < 16) ? Wq[(size_t)o * C + c] * LOG2E
                                : Wk[(size_t)(o - 16) * C + c];
        }
    }
    __syncthreads();

    const int n0 = blockIdx.x * 512 + 2 * t;
    const float* xb = x + (size_t)b * C * N + n0;

    u64 a0[16], a1[16];
    if (z < 8) {
        #pragma unroll
        for (int j = 0; j < 16; j++) {
            a0[j] = pk2(bv[z * 32 + 2 * j], bv[z * 32 + 2 * j + 1]);
            a1[j] = a0[j];
        }
    } else {
        #pragma unroll
        for (int j = 0; j < 16; j++) {
            a0[j] = (j < 8) ? pk2(bq[2 * j] * LOG2E, bq[2 * j + 1] * LOG2E)
                            : pk2(bk[2 * (j - 8)], bk[2 * (j - 8) + 1]);
            a1[j] = a0[j];
        }
    }

    #pragma unroll 4
    for (int c = 0; c < C; c++) {
        float2 xv = *(const float2*)&xb[(size_t)c * N];
        u64 xx0 = pk2(xv.x, xv.x);
        u64 xx1 = pk2(xv.y, xv.y);
        const u64* wr = (const u64*)&w_t[c * 32];
        #pragma unroll
        for (int j = 0; j < 16; j++) {
            u64 w = wr[j];
            a0[j] = fma2(xx0, w, a0[j]);
            a1[j] = fma2(xx1, w, a1[j]);
        }
    }

    if (z < 8) {
        #pragma unroll
        for (int j = 0; j < 16; j++) {
            float2 f0 = up2(a0[j]);
            float2 f1 = up2(a1[j]);
            size_t r0 = ((size_t)b * C + z * 32 + 2 * j) * N + n0;
            *(u16*)(g_v + r0)     = e4m3f2(f0.x, f1.x);
            *(u16*)(g_v + r0 + N) = e4m3f2(f0.y, f1.y);
        }
    } else {
        u32 w0[8], w1[8], k0[8], k1[8];
        #pragma unroll
        for (int j = 0; j < 8; j++) {
            float2 q0 = up2(a0[j]),      q1 = up2(a1[j]);
            float2 kk0 = up2(a0[j + 8]), kk1 = up2(a1[j + 8]);
            w0[j] = bf2(q0.x, q0.y);   w1[j] = bf2(q1.x, q1.y);
            k0[j] = bf2(kk0.x, kk0.y); k1[j] = bf2(kk1.x, kk1.y);
        }
        uint4* qd = (uint4*)&g_q[((size_t)b * N + n0) * CQK];
        qd[0] = make_uint4(w0[0], w0[1], w0[2], w0[3]);
        qd[1] = make_uint4(w0[4], w0[5], w0[6], w0[7]);
        qd[2] = make_uint4(w1[0], w1[1], w1[2], w1[3]);
        qd[3] = make_uint4(w1[4], w1[5], w1[6], w1[7]);
        uint4* kd = (uint4*)&g_k[((size_t)b * N + n0) * CQK];
        kd[0] = make_uint4(k0[0], k0[1], k0[2], k0[3]);
        kd[1] = make_uint4(k0[4], k0[5], k0[6], k0[7]);
        kd[2] = make_uint4(k1[0], k1[1], k1[2], k1[3]);
        kd[3] = make_uint4(k1[4], k1[5], k1[6], k1[7]);
    }
}

// ---------------------------------------------------------------------------
// Flash attention, 2 CTAs/SM, fp8 PV — addressing-free inner loop.
// ---------------------------------------------------------------------------
#define QKS 48
#define PS  80
#define VS  80
#define SM_L   0
#define SM_K   512                   // [64][QKS]
#define SM_Q   (SM_K + 64*QKS)       // 3 x [64][QKS]
#define SM_P   (SM_Q + 3*64*QKS)     // 2 x [64][PS]
#define SM_V   (SM_P + 2*64*PS)      // 3 x [256][VS]
#define SM_TOTAL (SM_V + 3*256*VS)

#define QBUF (64*QKS)
#define PBUF (64*PS)
#define VBUF (256*VS)

__global__ __launch_bounds__(256, 2) void attn_kernel(
    const float* __restrict__ x,
    const float* __restrict__ gamma,
    float* __restrict__ out)
{
    extern __shared__ char smc[];
    float* L_s = (float*)(smc + SM_L);
    const u32 sbase = smem_u32(smc);

    const int t    = threadIdx.x;
    const int bb   = blockIdx.y;
    const int m0   = blockIdx.x * MT;
    const int lane = t & 31;
    const int w    = t >> 5;

    const int mt = w & 3;            // S: m16-tile
    const int nh = w >> 2;           // S: n32-half
    const int ct0 = w * 32;          // PV: c32-tile

    const int lj = lane >> 3;
    const int li = lane & 7;
    const int r  = lane >> 2;
    const int cq = lane & 3;

    const int ldA = (lj & 1) * 8 + li;   // A-frag row / col bits
    const int ldAc = (lj >> 1) * 16;
    const int ldB = (lj >> 1) * 8 + li;  // B-frag row / col bits
    const int ldBc = (lj & 1) * 16;

    // ---- precomputed per-warp fragment address constants (sbase folded in) ----
    const u32 qfrag0 = sbase + SM_Q + (u32)((nh * 32 +      ldB) * QKS + ldBc);
    const u32 qfrag1 = sbase + SM_Q + (u32)((nh * 32 + 16 + ldB) * QKS + ldBc);
    u32 vfrag[2][2], pfrag[4][2];
    #pragma unroll
    for (int ct = 0; ct < 2; ct++)
        #pragma unroll
        for (int ks = 0; ks < 2; ks++)
            vfrag[ct][ks] = sbase + SM_V + (u32)((ct0 + ct * 16 + ldA) * VS + ks * 32 + ldAc);
    #pragma unroll
    for (int mp = 0; mp < 4; mp++)
        #pragma unroll
        for (int ks = 0; ks < 2; ks++)
            pfrag[mp][ks] = sbase + SM_P + (u32)((mp * 16 + ldB) * PS + ks * 32 + ldBc);
    char* const psto0 = smc + SM_P + (mt * 16 + r)     * PS + nh * 32 + 2 * cq;
    char* const psto1 = smc + SM_P + (mt * 16 + r + 8) * PS + nh * 32 + 2 * cq;

    // ---- init: L, K tile ----
    if (t < MT) L_s[t] = 0.f;
    if (t < 128) {
        int m = t >> 1, half = t & 1;
        *(uint4*)(smc + SM_K + m * QKS + half * 16) =
            *(const uint4*)(g_k + ((size_t)bb * N + m0 + m) * CQK + half * 8);
    }

    // ---- running gmem pointers (advance by constants) ----
    const __nv_bfloat16* gq_p =
        g_q + ((size_t)bb * N + (t >> 1)) * CQK + (size_t)(t & 1) * 8;
    const u8* gv_p = g_v + ((size_t)bb * C + (t >> 2)) * N + (size_t)(t & 3) * 16;
    char* const qsto = smc + SM_Q + (t >> 1) * QKS + (t & 1) * 16;   // t<128 only
    char* const vsto = smc + SM_V + (t >> 2) * VS + (t & 3) * 16;

    auto load_qv = [&](u32 qWo, u32 vWo) {
        if (t < 128) {
            *(uint4*)(qsto + qWo) = *(const uint4*)gq_p;
            gq_p += NT * CQK;
        }
        char* vd = vsto + vWo;
        #pragma unroll
        for (int i4 = 0; i4 < 4; i4++)
            *(uint4*)(vd + i4 * (64 * VS)) =
                *(const uint4*)(gv_p + (size_t)i4 * 64 * N);
        gv_p += NT;
    };

    // prologue: tiles 0,1 into bufs 0,1
    load_qv(0, 0);
    load_qv(QBUF, VBUF);
    __syncthreads();

    // hoisted K A-frag (constant per block)
    u32 aK[4];
    ldsm4(aK, sbase + SM_K + (u32)((mt * 16 + ldA) * QKS + ldAc));

    float Lacc0 = 0.f, Lacc8 = 0.f;

    auto s_compute = [&](u32 qRo, u32 pWo) {
        u32 b0[4], b1[4];
        ldsm4(b0, qfrag0 + qRo);
        ldsm4(b1, qfrag1 + qRo);

        float d[4][4];
        #pragma unroll
        for (int j = 0; j < 4; j++)
            #pragma unroll
            for (int e = 0; e < 4; e++) d[j][e] = -SBIAS;
        mma_bf16(d[0], aK, b0);
        mma_bf16(d[1], aK, b0 + 2);
        mma_bf16(d[2], aK, b1);
        mma_bf16(d[3], aK, b1 + 2);

        char* pb0 = psto0 + pWo;
        char* pb1 = psto1 + pWo;
        u32 Lt0 = 0, Lt8 = 0;
        #pragma unroll
        for (int nt = 0; nt < 4; nt++) {
            u32 e0 = ex2h2(hpack(d[nt][0], d[nt][1]));
            u32 e1 = ex2h2(hpack(d[nt][2], d[nt][3]));
            Lt0 = hadd2(Lt0, e0);
            Lt8 = hadd2(Lt8, e1);
            *(u16*)(pb0 + nt * 8) = e4m3h2(e0);
            *(u16*)(pb1 + nt * 8) = e4m3h2(e1);
        }
        Lacc0 += h2sum(Lt0);
        Lacc8 += h2sum(Lt8);
    };

    float d_acc[2][8][4];
    #pragma unroll
    for (int ct = 0; ct < 2; ct++)
        #pragma unroll
        for (int mp = 0; mp < 8; mp++)
            #pragma unroll
            for (int e = 0; e < 4; e++) d_acc[ct][mp][e] = 0.f;

    s_compute(0, 0);        // S(0): Q buf0 -> P buf0
    __syncthreads();

    // rotating buffer offsets (registers; no % in loop)
    u32 qRo = QBUF, qIo = 0, qWo = 2 * QBUF;            // read(t+1) / idle / write(t+2)
    u32 vPVo = 0, vIo = VBUF, vWo = 2 * VBUF;           // pv-read(t) / idle / write(t+2)
    u32 pWo = PBUF, pRo = 0;                            // write(t+1) / pv-read(t)

    for (int tile = 0; tile < NTILES; ++tile) {
        if (tile + 2 < NTILES) load_qv(qWo, vWo);
        if (tile + 1 < NTILES) s_compute(qRo, pWo);

        // ---- PV: O += V(tile) @ P^T(tile), fp8 ----
        #pragma unroll
        for (int ks = 0; ks < 2; ks++) {
            u32 av[2][4];
            ldsm4(av[0], vfrag[0][ks] + vPVo);
            ldsm4(av[1], vfrag[1][ks] + vPVo);
            #pragma unroll
            for (int mp = 0; mp < 4; mp++) {
                u32 bf[4];
                ldsm4(bf, pfrag[mp][ks] + pRo);
                mma_e4m3(d_acc[0][2 * mp    ], av[0], bf);
                mma_e4m3(d_acc[0][2 * mp + 1], av[0], bf + 2);
                mma_e4m3(d_acc[1][2 * mp    ], av[1], bf);
                mma_e4m3(d_acc[1][2 * mp + 1], av[1], bf + 2);
            }
        }
        __syncthreads();

        // rotate buffers
        u32 tq = qRo; qRo = qWo; qWo = qIo; qIo = tq;
        u32 tv = vPVo; vPVo = vIo; vIo = vWo; vWo = tv;
        pWo ^= PBUF; pRo ^= PBUF;
    }

    // ---- L reduction (once) ----
    Lacc0 += __shfl_xor_sync(0xffffffffu, Lacc0, 1);
    Lacc0 += __shfl_xor_sync(0xffffffffu, Lacc0, 2);
    Lacc8 += __shfl_xor_sync(0xffffffffu, Lacc8, 1);
    Lacc8 += __shfl_xor_sync(0xffffffffu, Lacc8, 2);
    if (cq == 0) {
        atomicAdd(&L_s[mt * 16 + r],     Lacc0);
        atomicAdd(&L_s[mt * 16 + r + 8], Lacc8);
    }
    __syncthreads();
    if (t < MT) L_s[t] = 1.0f / fmaxf(L_s[t], 1e-30f);
    __syncthreads();

    // ---- epilogue: out = x + gamma * O / L ----
    const float g = gamma[0];
    #pragma unroll
    for (int ct = 0; ct < 2; ct++) {
        #pragma unroll
        for (int half = 0; half < 2; half++) {
            int c = ct0 + ct * 16 + r + half * 8;
            #pragma unroll
            for (int mp = 0; mp < 8; mp++) {
                int mloc = mp * 8 + cq * 2;
                float iL0 = L_s[mloc], iL1 = L_s[mloc + 1];
                size_t idx = ((size_t)bb * C + c) * N + m0 + mloc;
                float2 xv = *(const float2*)&x[idx];
                float2 ov;
                ov.x = xv.x + g * d_acc[ct][mp][half * 2    ] * iL0;
                ov.y = xv.y + g * d_acc[ct][mp][half * 2 + 1] * iL1;
                *(float2*)&out[idx] = ov;
            }
        }
    }
}

// ---------------------------------------------------------------------------
extern "C" void kernel_launch(void* const* d_in, const int* in_sizes, int n_in,
                              void* d_out, int out_size)
{
    const float* x     = (const float*)d_in[0];
    const float* Wq    = (const float*)d_in[1];
    const float* bq    = (const float*)d_in[2];
    const float* Wk    = (const float*)d_in[3];
    const float* bk    = (const float*)d_in[4];
    const float* Wv    = (const float*)d_in[5];
    const float* bv    = (const float*)d_in[6];
    const float* gamma = (const float*)d_in[7];
    float* out = (float*)d_out;

    proj_kernel<<<dim3(N / 512, B, 9), 256>>>(x, Wq, bq, Wk, bk, Wv, bv);

    cudaFuncSetAttribute(attn_kernel,
                         cudaFuncAttributeMaxDynamicSharedMemorySize, SM_TOTAL);
    attn_kernel<<<dim3(N / MT, B), 256, SM_TOTAL>>>(x, gamma, out);
}

// round 12
// speedup vs baseline: 1.2190x; 1.2190x over previous
#include <cuda_runtime.h>
#include <cuda_bf16.h>

#define B    4
#define C    256
#define CQK  16
#define MT   64
#define NT   64
#define N    4096
#define NTILES (N / NT)
#define LOG2E 1.4426950408889634f
#define SBIAS 20.0f     // P = 2^(s*log2e - SBIAS); cancels in o/L

typedef unsigned long long u64;
typedef unsigned int u32;
typedef unsigned short u16;
typedef unsigned char u8;

// Scratch: q,k bf16 [B][N][16] (q pre-scaled by log2e); v e4m3 [B][C][N]
// g_w: packed weights bf16 [288][256]: rows 0-15 Wq*log2e, 16-31 Wk, 32-287 Wv
__device__ __nv_bfloat16 g_q[(size_t)B * N * CQK];
__device__ __nv_bfloat16 g_k[(size_t)B * N * CQK];
__device__ u8            g_v[(size_t)B * C * N];
__device__ __nv_bfloat16 g_w[288 * 256];

// ---- bf16 / f16 / fp8 helpers --------------------------------------------------
__device__ __forceinline__ u32 bf2(float lo, float hi) {
    u32 r; asm("cvt.rn.bf16x2.f32 %0,%1,%2;" : "=r"(r) : "f"(hi), "f"(lo)); return r;
}
__device__ __forceinline__ u32 hpack(float lo, float hi) {
    u32 r; asm("cvt.rn.f16x2.f32 %0,%1,%2;" : "=r"(r) : "f"(hi), "f"(lo)); return r;
}
__device__ __forceinline__ u32 ex2h2(u32 s) {
    u32 d; asm("ex2.approx.f16x2 %0,%1;" : "=r"(d) : "r"(s)); return d;
}
__device__ __forceinline__ u32 hadd2(u32 a, u32 b) {
    u32 d; asm("add.rn.f16x2 %0,%1,%2;" : "=r"(d) : "r"(a), "r"(b)); return d;
}
__device__ __forceinline__ u16 e4m3h2(u32 h) {
    u16 d; asm("cvt.rn.satfinite.e4m3x2.f16x2 %0,%1;" : "=h"(d) : "r"(h)); return d;
}
__device__ __forceinline__ u16 e4m3f2(float lo, float hi) {
    u16 d; asm("cvt.rn.satfinite.e4m3x2.f32 %0,%1,%2;" : "=h"(d) : "f"(hi), "f"(lo)); return d;
}
__device__ __forceinline__ float h2sum(u32 h) {
    float a, b;
    asm("{.reg .f16 x,y; mov.b32 {x,y},%2; cvt.f32.f16 %0,x; cvt.f32.f16 %1,y;}"
        : "=f"(a), "=f"(b) : "r"(h));
    return a + b;
}

// ---- tensor-core helpers (u32 shared addresses) ---------------------------------
__device__ __forceinline__ u32 smem_u32(const void* p) {
    u32 a;
    asm("{ .reg .u64 t; cvta.to.shared.u64 t, %1; cvt.u32.u64 %0, t; }" : "=r"(a) : "l"(p));
    return a;
}
__device__ __forceinline__ void ldsm4(u32* r, u32 a) {
    asm volatile("ldmatrix.sync.aligned.m8n8.x4.shared.b16 {%0,%1,%2,%3},[%4];"
                 : "=r"(r[0]), "=r"(r[1]), "=r"(r[2]), "=r"(r[3]) : "r"(a));
}
__device__ __forceinline__ void ldsm4t(u32* r, u32 a) {
    asm volatile("ldmatrix.sync.aligned.m8n8.x4.trans.shared.b16 {%0,%1,%2,%3},[%4];"
                 : "=r"(r[0]), "=r"(r[1]), "=r"(r[2]), "=r"(r[3]) : "r"(a));
}
__device__ __forceinline__ void mma_bf16(float* d, const u32* a, const u32* b) {
    asm volatile("mma.sync.aligned.m16n8k16.row.col.f32.bf16.bf16.f32 "
                 "{%0,%1,%2,%3},{%4,%5,%6,%7},{%8,%9},{%0,%1,%2,%3};"
                 : "+f"(d[0]), "+f"(d[1]), "+f"(d[2]), "+f"(d[3])
                 : "r"(a[0]), "r"(a[1]), "r"(a[2]), "r"(a[3]), "r"(b[0]), "r"(b[1]));
}
__device__ __forceinline__ void mma_e4m3(float* d, const u32* a, const u32* b) {
    asm volatile("mma.sync.aligned.m16n8k32.row.col.f32.e4m3.e4m3.f32 "
                 "{%0,%1,%2,%3},{%4,%5,%6,%7},{%8,%9},{%0,%1,%2,%3};"
                 : "+f"(d[0]), "+f"(d[1]), "+f"(d[2]), "+f"(d[3])
                 : "r"(a[0]), "r"(a[1]), "r"(a[2]), "r"(a[3]), "r"(b[0]), "r"(b[1]));
}
#define CP_COMMIT() asm volatile("cp.async.commit_group;" ::: "memory")
#define CP_WAIT1()  asm volatile("cp.async.wait_group 1;" ::: "memory")

// ---------------------------------------------------------------------------
// Weight pack: g_w[o][c] bf16; q rows pre-scaled by log2e. grid 288 x 256 thr.
// ---------------------------------------------------------------------------
__global__ void wcvt_kernel(const float* __restrict__ Wq,
                            const float* __restrict__ Wk,
                            const float* __restrict__ Wv)
{
    int idx = blockIdx.x * 256 + threadIdx.x;     // 0 .. 73727
    int o = idx >> 8, c = idx & 255;
    float v;
    if (o < 16)      v = Wq[o * C + c] * LOG2E;
    else if (o < 32) v = Wk[(o - 16) * C + c];
    else             v = Wv[(o - 32) * C + c];
    g_w[idx] = __float2bfloat16_rn(v);
}

// ---------------------------------------------------------------------------
// Tensor-core projection: out[288][64n] per block = W(bf16) @ x^T(bf16).
// grid (N/64, B), 256 thr (8 warps). Warp w: v-channels [32w,32w+32);
// warps 0/1 additionally q/k (16 rows each), reusing the same B fragments.
// ---------------------------------------------------------------------------
#define WS 80                         // W chunk row stride (64B data + 16)
#define XS 144                        // x chunk row stride (128B data + 16)
#define PM_W 0                        // 3 x [288][WS]
#define PM_X (3*288*WS)               // 3 x [32][XS]
#define PM_TOTAL (PM_X + 3*32*XS)     // 82,944 B

__global__ __launch_bounds__(256) void proj_mma_kernel(
    const float* __restrict__ x,
    const float* __restrict__ bq, const float* __restrict__ bk,
    const float* __restrict__ bv)
{
    extern __shared__ char smc[];
    const u32 sb = smem_u32(smc);
    const int t = threadIdx.x, lane = t & 31, w = t >> 5;
    const int b = blockIdx.y, n0 = blockIdx.x * 64;
    const int lj = lane >> 3, li = lane & 7, r = lane >> 2, cq = lane & 3;
    const int ldA  = (lj & 1) * 8 + li;
    const int ldAc = (lj >> 1) * 16;

    const float* xb = x + (size_t)b * C * N + n0;

    auto load_w = [&](int kc, int buf) {
        u32 dst = sb + PM_W + buf * (288 * WS);
        const char* src = (const char*)g_w + kc * 64;
        #pragma unroll
        for (int i = 0; i < 5; i++) {
            int idx = t + i * 256;
            if (idx < 1152) {
                int o = idx >> 2, col = idx & 3;
                asm volatile("cp.async.cg.shared.global [%0],[%1],16;"
                             :: "r"(dst + o * WS + col * 16),
                                "l"(src + o * 512 + col * 16) : "memory");
            }
        }
    };
    auto load_x = [&](int kc, int buf) {
        char* dst = smc + PM_X + buf * (32 * XS);
        #pragma unroll
        for (int i = 0; i < 2; i++) {
            int idx = t + i * 256;
            int c = idx >> 4, nq = idx & 15;
            float4 v4 = *(const float4*)(xb + (size_t)(kc * 32 + c) * N + nq * 4);
            *(uint2*)(dst + c * XS + nq * 8) =
                make_uint2(bf2(v4.x, v4.y), bf2(v4.z, v4.w));
        }
    };

    // accumulators with bias folded into init
    float d[2][8][4], dq[8][4];
    {
        float b0 = bv[w * 32 + r],      b1 = bv[w * 32 + r + 8];
        float b2 = bv[w * 32 + 16 + r], b3 = bv[w * 32 + 16 + r + 8];
        float c0 = 0.f, c1 = 0.f;
        if (w == 0) { c0 = bq[r] * LOG2E; c1 = bq[r + 8] * LOG2E; }
        if (w == 1) { c0 = bk[r];         c1 = bk[r + 8]; }
        #pragma unroll
        for (int jn = 0; jn < 8; jn++) {
            d[0][jn][0] = b0; d[0][jn][1] = b0; d[0][jn][2] = b1; d[0][jn][3] = b1;
            d[1][jn][0] = b2; d[1][jn][1] = b2; d[1][jn][2] = b3; d[1][jn][3] = b3;
            dq[jn][0] = c0; dq[jn][1] = c0; dq[jn][2] = c1; dq[jn][3] = c1;
        }
    }

    load_w(0, 0); load_x(0, 0); CP_COMMIT();
    load_w(1, 1); load_x(1, 1); CP_COMMIT();

    const int obase = 32 + w * 32;     // this warp's v rows in g_w

    #pragma unroll 1
    for (int kc = 0; kc < 8; kc++) {
        const int cur = kc % 3;
        CP_WAIT1();
        __syncthreads();
        if (kc + 2 < 8) { load_w(kc + 2, (kc + 2) % 3); load_x(kc + 2, (kc + 2) % 3); }
        CP_COMMIT();

        const u32 wbase = sb + PM_W + cur * (288 * WS);
        const u32 xbase = sb + PM_X + cur * (32 * XS);
        #pragma unroll
        for (int ks = 0; ks < 2; ks++) {
            u32 a0[4], a1[4], aq[4];
            ldsm4(a0, wbase + (u32)((obase      + ldA) * WS + ks * 32 + ldAc));
            ldsm4(a1, wbase + (u32)((obase + 16 + ldA) * WS + ks * 32 + ldAc));
            if (w < 2)
                ldsm4(aq, wbase + (u32)((w * 16 + ldA) * WS + ks * 32 + ldAc));
            #pragma unroll
            for (int nf = 0; nf < 4; nf++) {
                u32 bf[4];
                ldsm4t(bf, xbase + (u32)((ks * 16 + ldA) * XS + nf * 32 + ldAc));
                mma_bf16(d[0][2 * nf    ], a0, bf);
                mma_bf16(d[0][2 * nf + 1], a0, bf + 2);
                mma_bf16(d[1][2 * nf    ], a1, bf);
                mma_bf16(d[1][2 * nf + 1], a1, bf + 2);
                if (w < 2) {
                    mma_bf16(dq[2 * nf    ], aq, bf);
                    mma_bf16(dq[2 * nf + 1], aq, bf + 2);
                }
            }
        }
    }

    // ---- epilogue: v -> e4m3 g_v[c][n]; q/k -> bf16 [n][16] ----
    #pragma unroll
    for (int mi = 0; mi < 2; mi++) {
        int o = w * 32 + mi * 16 + r;
        u8* vrow0 = g_v + ((size_t)b * C + o) * N + n0;
        u8* vrow1 = vrow0 + (size_t)8 * N;
        #pragma unroll
        for (int jn = 0; jn < 8; jn++) {
            int nb = jn * 8 + 2 * cq;
            *(u16*)(vrow0 + nb) = e4m3f2(d[mi][jn][0], d[mi][jn][1]);
            *(u16*)(vrow1 + nb) = e4m3f2(d[mi][jn][2], d[mi][jn][3]);
        }
    }
    if (w < 2) {
        __nv_bfloat16* gqk = (w == 0 ? g_q : g_k) + (size_t)b * N * CQK;
        #pragma unroll
        for (int jn = 0; jn < 8; jn++) {
            int n = n0 + jn * 8 + 2 * cq;
            gqk[(size_t)n * CQK + r]           = __float2bfloat16_rn(dq[jn][0]);
            gqk[(size_t)(n + 1) * CQK + r]     = __float2bfloat16_rn(dq[jn][1]);
            gqk[(size_t)n * CQK + r + 8]       = __float2bfloat16_rn(dq[jn][2]);
            gqk[(size_t)(n + 1) * CQK + r + 8] = __float2bfloat16_rn(dq[jn][3]);
        }
    }
}

// ---------------------------------------------------------------------------
// Flash attention, 2 CTAs/SM, fp8 PV — addressing-free inner loop (R11).
// ---------------------------------------------------------------------------
#define QKS 48
#define PS  80
#define VS  80
#define SM_L   0
#define SM_K   512                   // [64][QKS]
#define SM_Q   (SM_K + 64*QKS)       // 3 x [64][QKS]
#define SM_P   (SM_Q + 3*64*QKS)     // 2 x [64][PS]
#define SM_V   (SM_P + 2*64*PS)      // 3 x [256][VS]
#define SM_TOTAL (SM_V + 3*256*VS)

#define QBUF (64*QKS)
#define PBUF (64*PS)
#define VBUF (256*VS)

__global__ __launch_bounds__(256, 2) void attn_kernel(
    const float* __restrict__ x,
    const float* __restrict__ gamma,
    float* __restrict__ out)
{
    extern __shared__ char smc[];
    float* L_s = (float*)(smc + SM_L);
    const u32 sbase = smem_u32(smc);

    const int t    = threadIdx.x;
    const int bb   = blockIdx.y;
    const int m0   = blockIdx.x * MT;
    const int lane = t & 31;
    const int w    = t >> 5;

    const int mt = w & 3;            // S: m16-tile
    const int nh = w >> 2;           // S: n32-half
    const int ct0 = w * 32;          // PV: c32-tile

    const int lj = lane >> 3;
    const int li = lane & 7;
    const int r  = lane >> 2;
    const int cq = lane & 3;

    const int ldA = (lj & 1) * 8 + li;
    const int ldAc = (lj >> 1) * 16;
    const int ldB = (lj >> 1) * 8 + li;
    const int ldBc = (lj & 1) * 16;

    const u32 qfrag0 = sbase + SM_Q + (u32)((nh * 32 +      ldB) * QKS + ldBc);
    const u32 qfrag1 = sbase + SM_Q + (u32)((nh * 32 + 16 + ldB) * QKS + ldBc);
    u32 vfrag[2][2], pfrag[4][2];
    #pragma unroll
    for (int ct = 0; ct < 2; ct++)
        #pragma unroll
        for (int ks = 0; ks < 2; ks++)
            vfrag[ct][ks] = sbase + SM_V + (u32)((ct0 + ct * 16 + ldA) * VS + ks * 32 + ldAc);
    #pragma unroll
    for (int mp = 0; mp < 4; mp++)
        #pragma unroll
        for (int ks = 0; ks < 2; ks++)
            pfrag[mp][ks] = sbase + SM_P + (u32)((mp * 16 + ldB) * PS + ks * 32 + ldBc);
    char* const psto0 = smc + SM_P + (mt * 16 + r)     * PS + nh * 32 + 2 * cq;
    char* const psto1 = smc + SM_P + (mt * 16 + r + 8) * PS + nh * 32 + 2 * cq;

    if (t < MT) L_s[t] = 0.f;
    if (t < 128) {
        int m = t >> 1, half = t & 1;
        *(uint4*)(smc + SM_K + m * QKS + half * 16) =
            *(const uint4*)(g_k + ((size_t)bb * N + m0 + m) * CQK + half * 8);
    }

    const __nv_bfloat16* gq_p =
        g_q + ((size_t)bb * N + (t >> 1)) * CQK + (size_t)(t & 1) * 8;
    const u8* gv_p = g_v + ((size_t)bb * C + (t >> 2)) * N + (size_t)(t & 3) * 16;
    char* const qsto = smc + SM_Q + (t >> 1) * QKS + (t & 1) * 16;
    char* const vsto = smc + SM_V + (t >> 2) * VS + (t & 3) * 16;

    auto load_qv = [&](u32 qWo, u32 vWo) {
        if (t < 128) {
            *(uint4*)(qsto + qWo) = *(const uint4*)gq_p;
            gq_p += NT * CQK;
        }
        char* vd = vsto + vWo;
        #pragma unroll
        for (int i4 = 0; i4 < 4; i4++)
            *(uint4*)(vd + i4 * (64 * VS)) =
                *(const uint4*)(gv_p + (size_t)i4 * 64 * N);
        gv_p += NT;
    };

    load_qv(0, 0);
    load_qv(QBUF, VBUF);
    __syncthreads();

    u32 aK[4];
    ldsm4(aK, sbase + SM_K + (u32)((mt * 16 + ldA) * QKS + ldAc));

    float Lacc0 = 0.f, Lacc8 = 0.f;

    auto s_compute = [&](u32 qRo, u32 pWo) {
        u32 b0[4], b1[4];
        ldsm4(b0, qfrag0 + qRo);
        ldsm4(b1, qfrag1 + qRo);

        float d[4][4];
        #pragma unroll
        for (int j = 0; j < 4; j++)
            #pragma unroll
            for (int e = 0; e < 4; e++) d[j][e] = -SBIAS;
        mma_bf16(d[0], aK, b0);
        mma_bf16(d[1], aK, b0 + 2);
        mma_bf16(d[2], aK, b1);
        mma_bf16(d[3], aK, b1 + 2);

        char* pb0 = psto0 + pWo;
        char* pb1 = psto1 + pWo;
        u32 Lt0 = 0, Lt8 = 0;
        #pragma unroll
        for (int nt = 0; nt < 4; nt++) {
            u32 e0 = ex2h2(hpack(d[nt][0], d[nt][1]));
            u32 e1 = ex2h2(hpack(d[nt][2], d[nt][3]));
            Lt0 = hadd2(Lt0, e0);
            Lt8 = hadd2(Lt8, e1);
            *(u16*)(pb0 + nt * 8) = e4m3h2(e0);
            *(u16*)(pb1 + nt * 8) = e4m3h2(e1);
        }
        Lacc0 += h2sum(Lt0);
        Lacc8 += h2sum(Lt8);
    };

    float d_acc[2][8][4];
    #pragma unroll
    for (int ct = 0; ct < 2; ct++)
        #pragma unroll
        for (int mp = 0; mp < 8; mp++)
            #pragma unroll
            for (int e = 0; e < 4; e++) d_acc[ct][mp][e] = 0.f;

    s_compute(0, 0);
    __syncthreads();

    u32 qRo = QBUF, qIo = 0, qWo = 2 * QBUF;
    u32 vPVo = 0, vIo = VBUF, vWo = 2 * VBUF;
    u32 pWo = PBUF, pRo = 0;

    for (int tile = 0; tile < NTILES; ++tile) {
        if (tile + 2 < NTILES) load_qv(qWo, vWo);
        if (tile + 1 < NTILES) s_compute(qRo, pWo);

        #pragma unroll
        for (int ks = 0; ks < 2; ks++) {
            u32 av[2][4];
            ldsm4(av[0], vfrag[0][ks] + vPVo);
            ldsm4(av[1], vfrag[1][ks] + vPVo);
            #pragma unroll
            for (int mp = 0; mp < 4; mp++) {
                u32 bf[4];
                ldsm4(bf, pfrag[mp][ks] + pRo);
                mma_e4m3(d_acc[0][2 * mp    ], av[0], bf);
                mma_e4m3(d_acc[0][2 * mp + 1], av[0], bf + 2);
                mma_e4m3(d_acc[1][2 * mp    ], av[1], bf);
                mma_e4m3(d_acc[1][2 * mp + 1], av[1], bf + 2);
            }
        }
        __syncthreads();

        u32 tq = qRo; qRo = qWo; qWo = qIo; qIo = tq;
        u32 tv = vPVo; vPVo = vIo; vIo = vWo; vWo = tv;
        pWo ^= PBUF; pRo ^= PBUF;
    }

    Lacc0 += __shfl_xor_sync(0xffffffffu, Lacc0, 1);
    Lacc0 += __shfl_xor_sync(0xffffffffu, Lacc0, 2);
    Lacc8 += __shfl_xor_sync(0xffffffffu, Lacc8, 1);
    Lacc8 += __shfl_xor_sync(0xffffffffu, Lacc8, 2);
    if (cq == 0) {
        atomicAdd(&L_s[mt * 16 + r],     Lacc0);
        atomicAdd(&L_s[mt * 16 + r + 8], Lacc8);
    }
    __syncthreads();
    if (t < MT) L_s[t] = 1.0f / fmaxf(L_s[t], 1e-30f);
    __syncthreads();

    const float g = gamma[0];
    #pragma unroll
    for (int ct = 0; ct < 2; ct++) {
        #pragma unroll
        for (int half = 0; half < 2; half++) {
            int c = ct0 + ct * 16 + r + half * 8;
            #pragma unroll
            for (int mp = 0; mp < 8; mp++) {
                int mloc = mp * 8 + cq * 2;
                float iL0 = L_s[mloc], iL1 = L_s[mloc + 1];
                size_t idx = ((size_t)bb * C + c) * N + m0 + mloc;
                float2 xv = *(const float2*)&x[idx];
                float2 ov;
                ov.x = xv.x + g * d_acc[ct][mp][half * 2    ] * iL0;
                ov.y = xv.y + g * d_acc[ct][mp][half * 2 + 1] * iL1;
                *(float2*)&out[idx] = ov;
            }
        }
    }
}

// ---------------------------------------------------------------------------
extern "C" void kernel_launch(void* const* d_in, const int* in_sizes, int n_in,
                              void* d_out, int out_size)
{
    const float* x     = (const float*)d_in[0];
    const float* Wq    = (const float*)d_in[1];
    const float* bq    = (const float*)d_in[2];
    const float* Wk    = (const float*)d_in[3];
    const float* bk    = (const float*)d_in[4];
    const float* Wv    = (const float*)d_in[5];
    const float* bv    = (const float*)d_in[6];
    const float* gamma = (const float*)d_in[7];
    float* out = (float*)d_out;

    wcvt_kernel<<<288, 256>>>(Wq, Wk, Wv);

    cudaFuncSetAttribute(proj_mma_kernel,
                         cudaFuncAttributeMaxDynamicSharedMemorySize, PM_TOTAL);
    proj_mma_kernel<<<dim3(N / 64, B), 256, PM_TOTAL>>>(x, bq, bk, bv);

    cudaFuncSetAttribute(attn_kernel,
                         cudaFuncAttributeMaxDynamicSharedMemorySize, SM_TOTAL);
    attn_kernel<<<dim3(N / MT, B), 256, SM_TOTAL>>>(x, gamma, out);
}

// round 13
// speedup vs baseline: 1.3107x; 1.0753x over previous
#include <cuda_runtime.h>
#include <cuda_bf16.h>

#define B    4
#define C    256
#define CQK  16
#define MT   64
#define NT   128
#define N    4096
#define NTILES (N / NT)
#define LOG2E 1.4426950408889634f
#define SBIAS 20.0f     // P = 2^(s*log2e - SBIAS); cancels in o/L

typedef unsigned long long u64;
typedef unsigned int u32;
typedef unsigned short u16;
typedef unsigned char u8;

// Scratch: q,k bf16 [B][N][16] (q pre-scaled by log2e); v e4m3 [B][C][N]
// g_w: packed weights bf16 [288][256]: rows 0-15 Wq*log2e, 16-31 Wk, 32-287 Wv
__device__ __nv_bfloat16 g_q[(size_t)B * N * CQK];
__device__ __nv_bfloat16 g_k[(size_t)B * N * CQK];
__device__ u8            g_v[(size_t)B * C * N];
__device__ __nv_bfloat16 g_w[288 * 256];

// ---- bf16 / f16 / fp8 helpers --------------------------------------------------
__device__ __forceinline__ u32 bf2(float lo, float hi) {
    u32 r; asm("cvt.rn.bf16x2.f32 %0,%1,%2;" : "=r"(r) : "f"(hi), "f"(lo)); return r;
}
__device__ __forceinline__ u32 hpack(float lo, float hi) {
    u32 r; asm("cvt.rn.f16x2.f32 %0,%1,%2;" : "=r"(r) : "f"(hi), "f"(lo)); return r;
}
__device__ __forceinline__ u32 ex2h2(u32 s) {
    u32 d; asm("ex2.approx.f16x2 %0,%1;" : "=r"(d) : "r"(s)); return d;
}
__device__ __forceinline__ u32 hadd2(u32 a, u32 b) {
    u32 d; asm("add.rn.f16x2 %0,%1,%2;" : "=r"(d) : "r"(a), "r"(b)); return d;
}
__device__ __forceinline__ u16 e4m3h2(u32 h) {
    u16 d; asm("cvt.rn.satfinite.e4m3x2.f16x2 %0,%1;" : "=h"(d) : "r"(h)); return d;
}
__device__ __forceinline__ u16 e4m3f2(float lo, float hi) {
    u16 d; asm("cvt.rn.satfinite.e4m3x2.f32 %0,%1,%2;" : "=h"(d) : "f"(hi), "f"(lo)); return d;
}
__device__ __forceinline__ float h2sum(u32 h) {
    float a, b;
    asm("{.reg .f16 x,y; mov.b32 {x,y},%2; cvt.f32.f16 %0,x; cvt.f32.f16 %1,y;}"
        : "=f"(a), "=f"(b) : "r"(h));
    return a + b;
}

// ---- tensor-core helpers (u32 shared addresses) ---------------------------------
__device__ __forceinline__ u32 smem_u32(const void* p) {
    u32 a;
    asm("{ .reg .u64 t; cvta.to.shared.u64 t, %1; cvt.u32.u64 %0, t; }" : "=r"(a) : "l"(p));
    return a;
}
__device__ __forceinline__ void ldsm4(u32* r, u32 a) {
    asm volatile("ldmatrix.sync.aligned.m8n8.x4.shared.b16 {%0,%1,%2,%3},[%4];"
                 : "=r"(r[0]), "=r"(r[1]), "=r"(r[2]), "=r"(r[3]) : "r"(a));
}
__device__ __forceinline__ void ldsm4t(u32* r, u32 a) {
    asm volatile("ldmatrix.sync.aligned.m8n8.x4.trans.shared.b16 {%0,%1,%2,%3},[%4];"
                 : "=r"(r[0]), "=r"(r[1]), "=r"(r[2]), "=r"(r[3]) : "r"(a));
}
__device__ __forceinline__ void mma_bf16(float* d, const u32* a, const u32* b) {
    asm volatile("mma.sync.aligned.m16n8k16.row.col.f32.bf16.bf16.f32 "
                 "{%0,%1,%2,%3},{%4,%5,%6,%7},{%8,%9},{%0,%1,%2,%3};"
                 : "+f"(d[0]), "+f"(d[1]), "+f"(d[2]), "+f"(d[3])
                 : "r"(a[0]), "r"(a[1]), "r"(a[2]), "r"(a[3]), "r"(b[0]), "r"(b[1]));
}
__device__ __forceinline__ void mma_e4m3(float* d, const u32* a, const u32* b) {
    asm volatile("mma.sync.aligned.m16n8k32.row.col.f32.e4m3.e4m3.f32 "
                 "{%0,%1,%2,%3},{%4,%5,%6,%7},{%8,%9},{%0,%1,%2,%3};"
                 : "+f"(d[0]), "+f"(d[1]), "+f"(d[2]), "+f"(d[3])
                 : "r"(a[0]), "r"(a[1]), "r"(a[2]), "r"(a[3]), "r"(b[0]), "r"(b[1]));
}
#define CP_COMMIT() asm volatile("cp.async.commit_group;" ::: "memory")
#define CP_WAIT1()  asm volatile("cp.async.wait_group 1;" ::: "memory")

// ---------------------------------------------------------------------------
// Weight pack: g_w[o][c] bf16; q rows pre-scaled by log2e. grid 288 x 256 thr.
// ---------------------------------------------------------------------------
__global__ void wcvt_kernel(const float* __restrict__ Wq,
                            const float* __restrict__ Wk,
                            const float* __restrict__ Wv)
{
    int idx = blockIdx.x * 256 + threadIdx.x;
    int o = idx >> 8, c = idx & 255;
    float v;
    if (o < 16)      v = Wq[o * C + c] * LOG2E;
    else if (o < 32) v = Wk[(o - 16) * C + c];
    else             v = Wv[(o - 32) * C + c];
    g_w[idx] = __float2bfloat16_rn(v);
}

// ---------------------------------------------------------------------------
// Tensor-core projection (unchanged from R12).
// ---------------------------------------------------------------------------
#define WS 80
#define XS 144
#define PM_W 0
#define PM_X (3*288*WS)
#define PM_TOTAL (PM_X + 3*32*XS)

__global__ __launch_bounds__(256) void proj_mma_kernel(
    const float* __restrict__ x,
    const float* __restrict__ bq, const float* __restrict__ bk,
    const float* __restrict__ bv)
{
    extern __shared__ char smc[];
    const u32 sb = smem_u32(smc);
    const int t = threadIdx.x, lane = t & 31, w = t >> 5;
    const int b = blockIdx.y, n0 = blockIdx.x * 64;
    const int lj = lane >> 3, li = lane & 7, r = lane >> 2, cq = lane & 3;
    const int ldA  = (lj & 1) * 8 + li;
    const int ldAc = (lj >> 1) * 16;

    const float* xb = x + (size_t)b * C * N + n0;

    auto load_w = [&](int kc, int buf) {
        u32 dst = sb + PM_W + buf * (288 * WS);
        const char* src = (const char*)g_w + kc * 64;
        #pragma unroll
        for (int i = 0; i < 5; i++) {
            int idx = t + i * 256;
            if (idx < 1152) {
                int o = idx >> 2, col = idx & 3;
                asm volatile("cp.async.cg.shared.global [%0],[%1],16;"
                             :: "r"(dst + o * WS + col * 16),
                                "l"(src + o * 512 + col * 16) : "memory");
            }
        }
    };
    auto load_x = [&](int kc, int buf) {
        char* dst = smc + PM_X + buf * (32 * XS);
        #pragma unroll
        for (int i = 0; i < 2; i++) {
            int idx = t + i * 256;
            int c = idx >> 4, nq = idx & 15;
            float4 v4 = *(const float4*)(xb + (size_t)(kc * 32 + c) * N + nq * 4);
            *(uint2*)(dst + c * XS + nq * 8) =
                make_uint2(bf2(v4.x, v4.y), bf2(v4.z, v4.w));
        }
    };

    float d[2][8][4], dq[8][4];
    {
        float b0 = bv[w * 32 + r],      b1 = bv[w * 32 + r + 8];
        float b2 = bv[w * 32 + 16 + r], b3 = bv[w * 32 + 16 + r + 8];
        float c0 = 0.f, c1 = 0.f;
        if (w == 0) { c0 = bq[r] * LOG2E; c1 = bq[r + 8] * LOG2E; }
        if (w == 1) { c0 = bk[r];         c1 = bk[r + 8]; }
        #pragma unroll
        for (int jn = 0; jn < 8; jn++) {
            d[0][jn][0] = b0; d[0][jn][1] = b0; d[0][jn][2] = b1; d[0][jn][3] = b1;
            d[1][jn][0] = b2; d[1][jn][1] = b2; d[1][jn][2] = b3; d[1][jn][3] = b3;
            dq[jn][0] = c0; dq[jn][1] = c0; dq[jn][2] = c1; dq[jn][3] = c1;
        }
    }

    load_w(0, 0); load_x(0, 0); CP_COMMIT();
    load_w(1, 1); load_x(1, 1); CP_COMMIT();

    const int obase = 32 + w * 32;

    #pragma unroll 1
    for (int kc = 0; kc < 8; kc++) {
        const int cur = kc % 3;
        CP_WAIT1();
        __syncthreads();
        if (kc + 2 < 8) { load_w(kc + 2, (kc + 2) % 3); load_x(kc + 2, (kc + 2) % 3); }
        CP_COMMIT();

        const u32 wbase = sb + PM_W + cur * (288 * WS);
        const u32 xbase = sb + PM_X + cur * (32 * XS);
        #pragma unroll
        for (int ks = 0; ks < 2; ks++) {
            u32 a0[4], a1[4], aq[4];
            ldsm4(a0, wbase + (u32)((obase      + ldA) * WS + ks * 32 + ldAc));
            ldsm4(a1, wbase + (u32)((obase + 16 + ldA) * WS + ks * 32 + ldAc));
            if (w < 2)
                ldsm4(aq, wbase + (u32)((w * 16 + ldA) * WS + ks * 32 + ldAc));
            #pragma unroll
            for (int nf = 0; nf < 4; nf++) {
                u32 bf[4];
                ldsm4t(bf, xbase + (u32)((ks * 16 + ldA) * XS + nf * 32 + ldAc));
                mma_bf16(d[0][2 * nf    ], a0, bf);
                mma_bf16(d[0][2 * nf + 1], a0, bf + 2);
                mma_bf16(d[1][2 * nf    ], a1, bf);
                mma_bf16(d[1][2 * nf + 1], a1, bf + 2);
                if (w < 2) {
                    mma_bf16(dq[2 * nf    ], aq, bf);
                    mma_bf16(dq[2 * nf + 1], aq, bf + 2);
                }
            }
        }
    }

    #pragma unroll
    for (int mi = 0; mi < 2; mi++) {
        int o = w * 32 + mi * 16 + r;
        u8* vrow0 = g_v + ((size_t)b * C + o) * N + n0;
        u8* vrow1 = vrow0 + (size_t)8 * N;
        #pragma unroll
        for (int jn = 0; jn < 8; jn++) {
            int nb = jn * 8 + 2 * cq;
            *(u16*)(vrow0 + nb) = e4m3f2(d[mi][jn][0], d[mi][jn][1]);
            *(u16*)(vrow1 + nb) = e4m3f2(d[mi][jn][2], d[mi][jn][3]);
        }
    }
    if (w < 2) {
        __nv_bfloat16* gqk = (w == 0 ? g_q : g_k) + (size_t)b * N * CQK;
        #pragma unroll
        for (int jn = 0; jn < 8; jn++) {
            int n = n0 + jn * 8 + 2 * cq;
            gqk[(size_t)n * CQK + r]           = __float2bfloat16_rn(dq[jn][0]);
            gqk[(size_t)(n + 1) * CQK + r]     = __float2bfloat16_rn(dq[jn][1]);
            gqk[(size_t)n * CQK + r + 8]       = __float2bfloat16_rn(dq[jn][2]);
            gqk[(size_t)(n + 1) * CQK + r + 8] = __float2bfloat16_rn(dq[jn][3]);
        }
    }
}

// ---------------------------------------------------------------------------
// Flash attention, 2 CTAs/SM, fp8 PV, NT=128 (32 tiles, 1 barrier each).
// ---------------------------------------------------------------------------
#define QKS 48
#define PS  144                      // P^T row stride (128 fp8 + 16)
#define VS  144                      // V row stride  (128 fp8 + 16)
#define SM_L   0
#define SM_K   512                   // [64][QKS]
#define SM_Q   (SM_K + 64*QKS)       // 3 x [128][QKS]
#define SM_P   (SM_Q + 3*128*QKS)    // 2 x [64][PS]
#define SM_V   (SM_P + 2*64*PS)      // 2 x [256][VS]
#define SM_TOTAL (SM_V + 2*256*VS)   // 114,176 B -> 2 blocks/SM

#define QBUF (128*QKS)
#define PBUF (64*PS)
#define VBUF (256*VS)

__global__ __launch_bounds__(256, 2) void attn_kernel(
    const float* __restrict__ x,
    const float* __restrict__ gamma,
    float* __restrict__ out)
{
    extern __shared__ char smc[];
    float* L_s = (float*)(smc + SM_L);
    const u32 sbase = smem_u32(smc);

    const int t    = threadIdx.x;
    const int bb   = blockIdx.y;
    const int m0   = blockIdx.x * MT;
    const int lane = t & 31;
    const int w    = t >> 5;

    const int mt = w & 3;            // S: m16-tile
    const int nq = w >> 2;           // S: n64-group (0/1)
    const int ct0 = w * 32;          // PV: c32-tile

    const int lj = lane >> 3;
    const int li = lane & 7;
    const int r  = lane >> 2;
    const int cq = lane & 3;

    const int ldA = (lj & 1) * 8 + li;
    const int ldAc = (lj >> 1) * 16;
    const int ldB = (lj >> 1) * 8 + li;
    const int ldBc = (lj & 1) * 16;

    // S: B-frag base addresses for this warp's n64 range (2 x n32 halves)
    const u32 qfragA = sbase + SM_Q + (u32)((nq * 64 +      ldB) * QKS + ldBc);
    const u32 qfragB = sbase + SM_Q + (u32)((nq * 64 + 16 + ldB) * QKS + ldBc);
    // PV: base fragment addresses (ks=0); +ks*32 inline
    u32 vfrag[2], pfrag[4];
    #pragma unroll
    for (int ct = 0; ct < 2; ct++)
        vfrag[ct] = sbase + SM_V + (u32)((ct0 + ct * 16 + ldA) * VS + ldAc);
    #pragma unroll
    for (int mp = 0; mp < 4; mp++)
        pfrag[mp] = sbase + SM_P + (u32)((mp * 16 + ldB) * PS + ldBc);
    char* const psto0 = smc + SM_P + (mt * 16 + r)     * PS + nq * 64 + 2 * cq;
    char* const psto1 = smc + SM_P + (mt * 16 + r + 8) * PS + nq * 64 + 2 * cq;

    if (t < MT) L_s[t] = 0.f;
    if (t < 128) {
        int m = t >> 1, half = t & 1;
        *(uint4*)(smc + SM_K + m * QKS + half * 16) =
            *(const uint4*)(g_k + ((size_t)bb * N + m0 + m) * CQK + half * 8);
    }

    // running gmem pointers
    const __nv_bfloat16* gq_p =
        g_q + ((size_t)bb * N + (t >> 1)) * CQK + (size_t)(t & 1) * 8;
    const u8* gv_p = g_v + ((size_t)bb * C + (t >> 3)) * N + (size_t)(t & 7) * 16;
    char* const qsto = smc + SM_Q + (t >> 1) * QKS + (t & 1) * 16;
    char* const vsto = smc + SM_V + (t >> 3) * VS + (t & 7) * 16;

    auto load_q = [&](u32 qWo) {
        *(uint4*)(qsto + qWo) = *(const uint4*)gq_p;
        gq_p += NT * CQK;
    };
    auto load_v = [&](u32 vWo) {
        char* vd = vsto + vWo;
        #pragma unroll
        for (int i8 = 0; i8 < 8; i8++)
            *(uint4*)(vd + i8 * (32 * VS)) =
                *(const uint4*)(gv_p + (size_t)i8 * 32 * N);
        gv_p += NT;
    };

    // prologue: Q(0), V(0), Q(1)
    load_q(0);
    load_v(0);
    load_q(QBUF);
    __syncthreads();

    u32 aK[4];
    ldsm4(aK, sbase + SM_K + (u32)((mt * 16 + ldA) * QKS + ldAc));

    float Lacc0 = 0.f, Lacc8 = 0.f;

    auto s_compute = [&](u32 qRo, u32 pWo) {
        u32 Lt0 = 0, Lt8 = 0;
        char* pb0 = psto0 + pWo;
        char* pb1 = psto1 + pWo;
        #pragma unroll
        for (int nh2 = 0; nh2 < 2; nh2++) {
            u32 b0[4], b1[4];
            ldsm4(b0, qfragA + qRo + nh2 * (32 * QKS));
            ldsm4(b1, qfragB + qRo + nh2 * (32 * QKS));

            float d[4][4];
            #pragma unroll
            for (int j = 0; j < 4; j++)
                #pragma unroll
                for (int e = 0; e < 4; e++) d[j][e] = -SBIAS;
            mma_bf16(d[0], aK, b0);
            mma_bf16(d[1], aK, b0 + 2);
            mma_bf16(d[2], aK, b1);
            mma_bf16(d[3], aK, b1 + 2);

            #pragma unroll
            for (int nt = 0; nt < 4; nt++) {
                u32 e0 = ex2h2(hpack(d[nt][0], d[nt][1]));
                u32 e1 = ex2h2(hpack(d[nt][2], d[nt][3]));
                Lt0 = hadd2(Lt0, e0);
                Lt8 = hadd2(Lt8, e1);
                *(u16*)(pb0 + nh2 * 32 + nt * 8) = e4m3h2(e0);
                *(u16*)(pb1 + nh2 * 32 + nt * 8) = e4m3h2(e1);
            }
        }
        Lacc0 += h2sum(Lt0);
        Lacc8 += h2sum(Lt8);
    };

    float d_acc[2][8][4];
    #pragma unroll
    for (int ct = 0; ct < 2; ct++)
        #pragma unroll
        for (int mp = 0; mp < 8; mp++)
            #pragma unroll
            for (int e = 0; e < 4; e++) d_acc[ct][mp][e] = 0.f;

    s_compute(0, 0);
    __syncthreads();

    u32 qRo = QBUF, qIo = 0, qWo = 2 * QBUF;
    u32 vRo = 0, vWo = VBUF;
    u32 pWo = PBUF, pRo = 0;

    for (int tile = 0; tile < NTILES; ++tile) {
        if (tile + 2 < NTILES) load_q(qWo);
        if (tile + 1 < NTILES) { load_v(vWo); s_compute(qRo, pWo); }

        // ---- PV: O += V(tile) @ P^T(tile), fp8, ks = 4 x k32 ----
        #pragma unroll
        for (int ks = 0; ks < 4; ks++) {
            u32 av[2][4];
            ldsm4(av[0], vfrag[0] + vRo + ks * 32);
            ldsm4(av[1], vfrag[1] + vRo + ks * 32);
            #pragma unroll
            for (int mp = 0; mp < 4; mp++) {
                u32 bf[4];
                ldsm4(bf, pfrag[mp] + pRo + ks * 32);
                mma_e4m3(d_acc[0][2 * mp    ], av[0], bf);
                mma_e4m3(d_acc[0][2 * mp + 1], av[0], bf + 2);
                mma_e4m3(d_acc[1][2 * mp    ], av[1], bf);
                mma_e4m3(d_acc[1][2 * mp + 1], av[1], bf + 2);
            }
        }
        __syncthreads();

        u32 tq = qRo; qRo = qWo; qWo = qIo; qIo = tq;
        vRo ^= VBUF; vWo ^= VBUF;
        pWo ^= PBUF; pRo ^= PBUF;
    }

    // ---- L reduction (once) ----
    Lacc0 += __shfl_xor_sync(0xffffffffu, Lacc0, 1);
    Lacc0 += __shfl_xor_sync(0xffffffffu, Lacc0, 2);
    Lacc8 += __shfl_xor_sync(0xffffffffu, Lacc8, 1);
    Lacc8 += __shfl_xor_sync(0xffffffffu, Lacc8, 2);
    if (cq == 0) {
        atomicAdd(&L_s[mt * 16 + r],     Lacc0);
        atomicAdd(&L_s[mt * 16 + r + 8], Lacc8);
    }
    __syncthreads();
    if (t < MT) L_s[t] = 1.0f / fmaxf(L_s[t], 1e-30f);
    __syncthreads();

    // ---- epilogue: out = x + gamma * O / L ----
    const float g = gamma[0];
    #pragma unroll
    for (int ct = 0; ct < 2; ct++) {
        #pragma unroll
        for (int half = 0; half < 2; half++) {
            int c = ct0 + ct * 16 + r + half * 8;
            #pragma unroll
            for (int mp = 0; mp < 8; mp++) {
                int mloc = mp * 8 + cq * 2;
                float iL0 = L_s[mloc], iL1 = L_s[mloc + 1];
                size_t idx = ((size_t)bb * C + c) * N + m0 + mloc;
                float2 xv = *(const float2*)&x[idx];
                float2 ov;
                ov.x = xv.x + g * d_acc[ct][mp][half * 2    ] * iL0;
                ov.y = xv.y + g * d_acc[ct][mp][half * 2 + 1] * iL1;
                *(float2*)&out[idx] = ov;
            }
        }
    }
}

// ---------------------------------------------------------------------------
extern "C" void kernel_launch(void* const* d_in, const int* in_sizes, int n_in,
                              void* d_out, int out_size)
{
    const float* x     = (const float*)d_in[0];
    const float* Wq    = (const float*)d_in[1];
    const float* bq    = (const float*)d_in[2];
    const float* Wk    = (const float*)d_in[3];
    const float* bk    = (const float*)d_in[4];
    const float* Wv    = (const float*)d_in[5];
    const float* bv    = (const float*)d_in[6];
    const float* gamma = (const float*)d_in[7];
    float* out = (float*)d_out;

    wcvt_kernel<<<288, 256>>>(Wq, Wk, Wv);

    cudaFuncSetAttribute(proj_mma_kernel,
                         cudaFuncAttributeMaxDynamicSharedMemorySize, PM_TOTAL);
    proj_mma_kernel<<<dim3(N / 64, B), 256, PM_TOTAL>>>(x, bq, bk, bv);

    cudaFuncSetAttribute(attn_kernel,
                         cudaFuncAttributeMaxDynamicSharedMemorySize, SM_TOTAL);
    attn_kernel<<<dim3(N / MT, B), 256, SM_TOTAL>>>(x, gamma, out);
}